// round 2
// baseline (speedup 1.0000x reference)
#include <cuda_runtime.h>
#include <math.h>

// Problem constants (fixed by the dataset)
#define NT   8192   // tokens
#define DIM  2048   // model dim (K for gemm1/2, N for gemm3)
#define HID  1408   // hidden (N for gemm1/2, K for gemm3)
#define NE   8      // experts
#define CAP  1024   // tokens per expert slot (NT/NE)

// Scratch: u = x@w1^T, h = silu(u) * (x@w3^T)   [NT, HID] each
__device__ float g_u[(size_t)NT * HID];
__device__ float g_h[(size_t)NT * HID];

#define BM 128
#define BN 128
#define BK 16

// EPI = 0 : C(g_u)[slot] = x @ w1^T tile
// EPI = 1 : C(g_h)[slot] = silu(g_u) * (x @ w3^T)
// EPI = 2 : out[start+row] = g_h @ w2^T tile (masked ragged scatter)
template <int EPI>
__global__ __launch_bounds__(256)
void gemm_grouped(const float* __restrict__ A_in,   // x for EPI 0/1; unused for EPI 2
                  const float* __restrict__ B_all,  // [E, N, K] expert weights
                  float* __restrict__ Cout,         // out for EPI 2; unused otherwise
                  const int* __restrict__ counts,
                  int N, int K)
{
    const int e  = blockIdx.z;
    const int bn = blockIdx.x;     // N tile
    const int bm = blockIdx.y;     // M tile within expert

    // prefix sum of counts -> start offset of this expert's tokens
    int start = 0;
#pragma unroll
    for (int j = 0; j < NE; ++j)
        if (j < e) start += counts[j];
    const int cnt = counts[e];
    // clamp like jax.lax.dynamic_slice for the input slice
    int start_cl = start;
    if (start_cl > NT - CAP) start_cl = NT - CAP;
    if (start_cl < 0) start_cl = 0;

    const float* A;
    int a_row0;
    if (EPI == 2) {
        A = g_h + (size_t)e * CAP * K;   // expert slot rows in scratch
        a_row0 = bm * BM;
    } else {
        A = A_in;                         // global token rows in x
        a_row0 = start_cl + bm * BM;
    }
    const float* B = B_all + (size_t)e * N * K + (size_t)(bn * BN) * K;

    __shared__ float As[BK][BM + 4];
    __shared__ float Bs[BK][BN + 4];

    const int tid = threadIdx.x;        // 256 threads
    const int tx = tid & 15;            // 0..15  -> N micro
    const int ty = tid >> 4;            // 0..15  -> M micro

    float acc[8][8];
#pragma unroll
    for (int i = 0; i < 8; ++i)
#pragma unroll
        for (int j = 0; j < 8; ++j) acc[i][j] = 0.f;

    for (int k0 = 0; k0 < K; k0 += BK) {
        // Load 128x16 tiles of A and B (512 float4 each, 2 per thread), transpose into smem
#pragma unroll
        for (int t = 0; t < 2; ++t) {
            int idx = tid + t * 256;
            int row = idx >> 2;
            int c4  = (idx & 3) * 4;
            float4 av = *(const float4*)(&A[(size_t)(a_row0 + row) * K + k0 + c4]);
            As[c4 + 0][row] = av.x;
            As[c4 + 1][row] = av.y;
            As[c4 + 2][row] = av.z;
            As[c4 + 3][row] = av.w;
            float4 bv = *(const float4*)(&B[(size_t)row * K + k0 + c4]);
            Bs[c4 + 0][row] = bv.x;
            Bs[c4 + 1][row] = bv.y;
            Bs[c4 + 2][row] = bv.z;
            Bs[c4 + 3][row] = bv.w;
        }
        __syncthreads();

#pragma unroll
        for (int k = 0; k < BK; ++k) {
            float a[8], b[8];
            float4 a0 = *(const float4*)(&As[k][ty * 8]);
            float4 a1 = *(const float4*)(&As[k][ty * 8 + 4]);
            float4 b0 = *(const float4*)(&Bs[k][tx * 8]);
            float4 b1 = *(const float4*)(&Bs[k][tx * 8 + 4]);
            a[0]=a0.x; a[1]=a0.y; a[2]=a0.z; a[3]=a0.w;
            a[4]=a1.x; a[5]=a1.y; a[6]=a1.z; a[7]=a1.w;
            b[0]=b0.x; b[1]=b0.y; b[2]=b0.z; b[3]=b0.w;
            b[4]=b1.x; b[5]=b1.y; b[6]=b1.z; b[7]=b1.w;
#pragma unroll
            for (int i = 0; i < 8; ++i)
#pragma unroll
                for (int j = 0; j < 8; ++j)
                    acc[i][j] = fmaf(a[i], b[j], acc[i][j]);
        }
        __syncthreads();
    }

    // Epilogue
#pragma unroll
    for (int i = 0; i < 8; ++i) {
        const int m_loc = bm * BM + ty * 8 + i;          // row within expert slot
#pragma unroll
        for (int j = 0; j < 8; ++j) {
            const int n = bn * BN + tx * 8 + j;
            if (EPI == 0) {
                g_u[(size_t)(e * CAP + m_loc) * N + n] = acc[i][j];
            } else if (EPI == 1) {
                size_t idx = (size_t)(e * CAP + m_loc) * N + n;
                float u = g_u[idx];
                float s = u / (1.f + expf(-u));          // silu(u)
                g_h[idx] = s * acc[i][j];
            } else {
                if (m_loc < cnt) {
                    int orow = start + m_loc;
                    if (orow < 0) orow = 0;
                    if (orow > NT - 1) orow = NT - 1;
                    Cout[(size_t)orow * N + n] = acc[i][j];
                }
            }
        }
    }
}

extern "C" void kernel_launch(void* const* d_in, const int* in_sizes, int n_in,
                              void* d_out, int out_size)
{
    const float* x      = (const float*)d_in[0];
    const int*   counts = (const int*)  d_in[1];
    const float* w1     = (const float*)d_in[2];
    const float* w2     = (const float*)d_in[3];
    const float* w3     = (const float*)d_in[4];
    float* out = (float*)d_out;

    // Zero output (ragged scatter only writes valid rows; balanced case writes all)
    cudaMemsetAsync(out, 0, (size_t)out_size * sizeof(float));

    dim3 blk(256);
    dim3 grid1(HID / BN, CAP / BM, NE);  // 11 x 8 x 8
    dim3 grid3(DIM / BN, CAP / BM, NE);  // 16 x 8 x 8

    // u = x @ w1^T
    gemm_grouped<0><<<grid1, blk>>>(x, w1, nullptr, counts, HID, DIM);
    // h = silu(u) * (x @ w3^T)
    gemm_grouped<1><<<grid1, blk>>>(x, w3, nullptr, counts, HID, DIM);
    // out = h @ w2^T  (masked scatter to token rows)
    gemm_grouped<2><<<grid3, blk>>>(nullptr, w2, out, counts, DIM, HID);
}

// round 8
// speedup vs baseline: 3.6817x; 3.6817x over previous
#include <cuda_runtime.h>
#include <cuda_fp16.h>
#include <stdint.h>
#include <math.h>

#define NT   8192
#define DIM  2048
#define HID  1408
#define NE   8
#define CAP  1024

// ---------------- device scratch ----------------
__device__ float  g_u [(size_t)NT * HID];           // x@w1^T fp32
__device__ __half g_xh[(size_t)NT * DIM];           // x hi
__device__ __half g_xl[(size_t)NT * DIM];           // x lo
__device__ __half g_hh[(size_t)NT * HID];           // h hi
__device__ __half g_hl[(size_t)NT * HID];           // h lo
__device__ __half g_w1h[(size_t)NE * HID * DIM];    // weights: single fp16
__device__ __half g_w3h[(size_t)NE * HID * DIM];
__device__ __half g_w2h[(size_t)NE * DIM * HID];

// ---------------- fp32 -> fp16 converters ----------------
__global__ __launch_bounds__(256)
void cvt_split(const float* __restrict__ src, __half* __restrict__ hi,
               __half* __restrict__ lo, int n4)
{
    int i = blockIdx.x * blockDim.x + threadIdx.x;
    if (i >= n4) return;
    float4 v = reinterpret_cast<const float4*>(src)[i];
    __half h0 = __float2half_rn(v.x), h1 = __float2half_rn(v.y);
    __half h2 = __float2half_rn(v.z), h3 = __float2half_rn(v.w);
    __half l0 = __float2half_rn(v.x - __half2float(h0));
    __half l1 = __float2half_rn(v.y - __half2float(h1));
    __half l2 = __float2half_rn(v.z - __half2float(h2));
    __half l3 = __float2half_rn(v.w - __half2float(h3));
    uint2 H, L;
    H.x = ((uint32_t)__half_as_ushort(h1) << 16) | __half_as_ushort(h0);
    H.y = ((uint32_t)__half_as_ushort(h3) << 16) | __half_as_ushort(h2);
    L.x = ((uint32_t)__half_as_ushort(l1) << 16) | __half_as_ushort(l0);
    L.y = ((uint32_t)__half_as_ushort(l3) << 16) | __half_as_ushort(l2);
    reinterpret_cast<uint2*>(hi)[i] = H;
    reinterpret_cast<uint2*>(lo)[i] = L;
}

__global__ __launch_bounds__(256)
void cvt_round(const float* __restrict__ src, __half* __restrict__ hi, int n4)
{
    int i = blockIdx.x * blockDim.x + threadIdx.x;
    if (i >= n4) return;
    float4 v = reinterpret_cast<const float4*>(src)[i];
    uint2 H;
    H.x = ((uint32_t)__half_as_ushort(__float2half_rn(v.y)) << 16) |
          __half_as_ushort(__float2half_rn(v.x));
    H.y = ((uint32_t)__half_as_ushort(__float2half_rn(v.w)) << 16) |
          __half_as_ushort(__float2half_rn(v.z));
    reinterpret_cast<uint2*>(hi)[i] = H;
}

// ---------------- HMMA grouped GEMM ----------------
#define BM 128
#define BN 128
#define BK 64
#define NSTAGE 3
#define TILE_B 16384                // 128 rows x 128B (BK=64 fp16)
#define STG_B  (3 * TILE_B)         // Ah, Al, B
#define SMEM_TOT (NSTAGE * STG_B)   // 147456

__device__ __forceinline__ uint32_t s2u(const void* p) {
    uint32_t r;
    asm("{ .reg .u64 t; cvta.to.shared.u64 t, %1; cvt.u32.u64 %0, t; }" : "=r"(r) : "l"(p));
    return r;
}

#define LDSM4(r, a) asm volatile( \
    "ldmatrix.sync.aligned.m8n8.x4.shared.b16 {%0,%1,%2,%3}, [%4];" \
    : "=r"((r)[0]), "=r"((r)[1]), "=r"((r)[2]), "=r"((r)[3]) : "r"(a))

#define MMA16816(d, a, b) asm volatile( \
    "mma.sync.aligned.m16n8k16.row.col.f32.f16.f16.f32 " \
    "{%0,%1,%2,%3}, {%4,%5,%6,%7}, {%8,%9}, {%0,%1,%2,%3};" \
    : "+f"((d)[0]), "+f"((d)[1]), "+f"((d)[2]), "+f"((d)[3]) \
    : "r"((a)[0]), "r"((a)[1]), "r"((a)[2]), "r"((a)[3]), "r"((b)[0]), "r"((b)[1]))

#define CPA16(s, g) asm volatile( \
    "cp.async.cg.shared.global [%0], [%1], 16;" :: "r"(s), "l"(g))

// EPI 0: g_u = x @ w1^T (fp32)
// EPI 1: h = silu(g_u) * (x @ w3^T) -> g_hh/g_hl fp16 split
// EPI 2: out = h @ w2^T (masked ragged scatter, fp32)
template <int EPI>
__global__ __launch_bounds__(256, 1)
void gemm_hmma(const __half* __restrict__ Ah, const __half* __restrict__ Al,
               const __half* __restrict__ Bw,
               float* __restrict__ Cout,
               __half* __restrict__ Hh, __half* __restrict__ Hl,
               const float* __restrict__ Uin,
               const int* __restrict__ counts, int N, int K)
{
    extern __shared__ char smem[];
    const int tid = threadIdx.x;
    const int e = blockIdx.z, bm = blockIdx.y, bn = blockIdx.x;

    int start = 0, cnt;
    {
        int c[NE];
#pragma unroll
        for (int j = 0; j < NE; ++j) c[j] = counts[j];
#pragma unroll
        for (int j = 0; j < NE; ++j) if (j < e) start += c[j];
        cnt = c[e];
    }
    int start_cl = start;
    if (start_cl > NT - CAP) start_cl = NT - CAP;
    if (start_cl < 0) start_cl = 0;

    const size_t a_row0 = (EPI == 2) ? ((size_t)e * CAP + (size_t)bm * BM)
                                     : ((size_t)start_cl + (size_t)bm * BM);
    const __half* Ahe = Ah + a_row0 * K;
    const __half* Ale = Al + a_row0 * K;
    const __half* Bwe = Bw + ((size_t)e * N + (size_t)bn * BN) * K;

    const uint32_t sb = s2u(smem);
    const int nch = K / BK;

    // ---- async stage loader: 3 tiles x 128 rows x 8 x 16B, SW128 swizzle ----
    auto load_stage = [&](int st, int cc) {
        const __half* s0 = Ahe + cc * BK;
        const __half* s1 = Ale + cc * BK;
        const __half* s2 = Bwe + cc * BK;
        const uint32_t sbase = sb + st * STG_B;
#pragma unroll
        for (int j = 0; j < 4; ++j) {
            int idx = tid + j * 256;
            int row = idx >> 3, g = idx & 7;
            uint32_t off = row * 128 + g * 16;
            off ^= (off >> 3) & 0x70;
            size_t go = (size_t)row * K + g * 8;
            CPA16(sbase + 0 * TILE_B + off, s0 + go);
            CPA16(sbase + 1 * TILE_B + off, s1 + go);
            CPA16(sbase + 2 * TILE_B + off, s2 + go);
        }
    };

    const int lane = tid & 31, wid = tid >> 5;
    const int wm = (wid & 3) * 32;        // warp m-offset (0..96)
    const int wn = (wid >> 2) * 64;       // warp n-offset (0 or 64)
    const int ln8 = lane & 7, sel = lane >> 3;

    float dacc[2][8][4];
#pragma unroll
    for (int i = 0; i < 2; ++i)
#pragma unroll
        for (int j = 0; j < 8; ++j)
#pragma unroll
            for (int k = 0; k < 4; ++k) dacc[i][j][k] = 0.f;

    // prologue
    load_stage(0, 0);
    asm volatile("cp.async.commit_group;" ::: "memory");
    if (nch > 1) load_stage(1, 1);
    asm volatile("cp.async.commit_group;" ::: "memory");

    for (int kc = 0; kc < nch; ++kc) {
        if (kc + 2 < nch) load_stage((kc + 2) % NSTAGE, kc + 2);
        asm volatile("cp.async.commit_group;" ::: "memory");
        asm volatile("cp.async.wait_group 2;" ::: "memory");
        __syncthreads();

        const int st = kc % NSTAGE;
        const uint32_t aB = sb + st * STG_B;
        const uint32_t lB = aB + TILE_B;
        const uint32_t bB = aB + 2 * TILE_B;

#pragma unroll
        for (int k16 = 0; k16 < 4; ++k16) {
            const int kb = k16 * 32;      // byte offset of this k16 within row
            uint32_t bfr[16];
#pragma unroll
            for (int np = 0; np < 4; ++np) {
                uint32_t off = (uint32_t)(wn + np * 16 + ln8 + ((sel >> 1) << 3)) * 128
                             + kb + ((sel & 1) << 4);
                off ^= (off >> 3) & 0x70;
                LDSM4(bfr + np * 4, bB + off);
            }
            uint32_t ahf[2][4], alf[2][4];
#pragma unroll
            for (int mf = 0; mf < 2; ++mf) {
                uint32_t off = (uint32_t)(wm + mf * 16 + (lane & 15)) * 128
                             + kb + ((lane >> 4) << 4);
                off ^= (off >> 3) & 0x70;
                LDSM4(ahf[mf], aB + off);
                LDSM4(alf[mf], lB + off);
            }
#pragma unroll
            for (int mf = 0; mf < 2; ++mf)
#pragma unroll
                for (int nf = 0; nf < 8; ++nf) {
                    MMA16816(dacc[mf][nf], ahf[mf], bfr + nf * 2);
                    MMA16816(dacc[mf][nf], alf[mf], bfr + nf * 2);
                }
        }
        __syncthreads();
    }

    // ---- epilogue ----
    const int lr = lane >> 2, lc = 2 * (lane & 3);
#pragma unroll
    for (int mf = 0; mf < 2; ++mf) {
#pragma unroll
        for (int p = 0; p < 2; ++p) {
            const int rloc = wm + mf * 16 + lr + p * 8;   // row in 128-tile
            const int mglob = bm * BM + rloc;             // row within expert slot
#pragma unroll
            for (int nf = 0; nf < 8; ++nf) {
                float v0 = dacc[mf][nf][p * 2 + 0];
                float v1 = dacc[mf][nf][p * 2 + 1];
                const int col = bn * BN + wn + nf * 8 + lc;
                if (EPI == 0) {
                    *(float2*)&Cout[((size_t)e * CAP + mglob) * HID + col] =
                        make_float2(v0, v1);
                } else if (EPI == 1) {
                    size_t ix = ((size_t)e * CAP + mglob) * HID + col;
                    float2 u = *(const float2*)&Uin[ix];
                    float h0 = (u.x / (1.f + expf(-u.x))) * v0;
                    float h1 = (u.y / (1.f + expf(-u.y))) * v1;
                    __half hh0 = __float2half_rn(h0), hh1 = __float2half_rn(h1);
                    __half hl0 = __float2half_rn(h0 - __half2float(hh0));
                    __half hl1 = __float2half_rn(h1 - __half2float(hh1));
                    *(__half2*)&Hh[ix] = __halves2half2(hh0, hh1);
                    *(__half2*)&Hl[ix] = __halves2half2(hl0, hl1);
                } else {
                    if (mglob < cnt) {
                        int orow = start + mglob;
                        if (orow < 0) orow = 0;
                        if (orow > NT - 1) orow = NT - 1;
                        *(float2*)&Cout[(size_t)orow * DIM + col] =
                            make_float2(v0, v1);
                    }
                }
            }
        }
    }
}

// ---------------- host launcher ----------------
extern "C" void kernel_launch(void* const* d_in, const int* in_sizes, int n_in,
                              void* d_out, int out_size)
{
    const float* x      = (const float*)d_in[0];
    const int*   counts = (const int*)  d_in[1];
    const float* w1     = (const float*)d_in[2];
    const float* w2     = (const float*)d_in[3];
    const float* w3     = (const float*)d_in[4];
    float* out = (float*)d_out;

    void *xh, *xl, *w1h, *w3h, *w2h, *uu, *hh, *hl;
    cudaGetSymbolAddress(&xh,  g_xh);  cudaGetSymbolAddress(&xl,  g_xl);
    cudaGetSymbolAddress(&w1h, g_w1h); cudaGetSymbolAddress(&w3h, g_w3h);
    cudaGetSymbolAddress(&w2h, g_w2h);
    cudaGetSymbolAddress(&uu,  g_u);
    cudaGetSymbolAddress(&hh,  g_hh);  cudaGetSymbolAddress(&hl,  g_hl);

    cudaMemsetAsync(out, 0, (size_t)out_size * sizeof(float));

    const int nx4 = NT * DIM / 4;
    const int nw4 = NE * HID * DIM / 4;
    cvt_split<<<(nx4 + 255) / 256, 256>>>(x, (__half*)xh, (__half*)xl, nx4);
    cvt_round<<<(nw4 + 255) / 256, 256>>>(w1, (__half*)w1h, nw4);
    cvt_round<<<(nw4 + 255) / 256, 256>>>(w3, (__half*)w3h, nw4);
    cvt_round<<<(nw4 + 255) / 256, 256>>>(w2, (__half*)w2h, nw4);

    cudaFuncSetAttribute(gemm_hmma<0>, cudaFuncAttributeMaxDynamicSharedMemorySize, SMEM_TOT);
    cudaFuncSetAttribute(gemm_hmma<1>, cudaFuncAttributeMaxDynamicSharedMemorySize, SMEM_TOT);
    cudaFuncSetAttribute(gemm_hmma<2>, cudaFuncAttributeMaxDynamicSharedMemorySize, SMEM_TOT);

    dim3 blk(256);
    dim3 g1(HID / BN, CAP / BM, NE);   // 11 x 8 x 8
    dim3 g3(DIM / BN, CAP / BM, NE);   // 16 x 8 x 8

    gemm_hmma<0><<<g1, blk, SMEM_TOT>>>(
        (const __half*)xh, (const __half*)xl, (const __half*)w1h,
        (float*)uu, nullptr, nullptr, nullptr, counts, HID, DIM);

    gemm_hmma<1><<<g1, blk, SMEM_TOT>>>(
        (const __half*)xh, (const __half*)xl, (const __half*)w3h,
        nullptr, (__half*)hh, (__half*)hl, (const float*)uu, counts, HID, DIM);

    gemm_hmma<2><<<g3, blk, SMEM_TOT>>>(
        (const __half*)hh, (const __half*)hl, (const __half*)w2h,
        out, nullptr, nullptr, nullptr, counts, DIM, HID);
}

// round 10
// speedup vs baseline: 6.7818x; 1.8420x over previous
#include <cuda_runtime.h>
#include <cuda_fp16.h>
#include <stdint.h>
#include <math.h>

#define NT   8192
#define DIM  2048
#define HID  1408
#define NE   8
#define CAP  1024

// ---------------- device scratch ----------------
__device__ __half g_xh[(size_t)NT * DIM];           // x fp16
__device__ __half g_hh[(size_t)NT * HID];           // h fp16
__device__ __half g_w1h[(size_t)NE * HID * DIM];
__device__ __half g_w3h[(size_t)NE * HID * DIM];
__device__ __half g_w2h[(size_t)NE * DIM * HID];

// ---------------- fp32 -> fp16 round ----------------
__global__ __launch_bounds__(256)
void cvt_round(const float* __restrict__ src, __half* __restrict__ hi, int n4)
{
    int i = blockIdx.x * blockDim.x + threadIdx.x;
    if (i >= n4) return;
    float4 v = reinterpret_cast<const float4*>(src)[i];
    uint2 H;
    H.x = ((uint32_t)__half_as_ushort(__float2half_rn(v.y)) << 16) |
          __half_as_ushort(__float2half_rn(v.x));
    H.y = ((uint32_t)__half_as_ushort(__float2half_rn(v.w)) << 16) |
          __half_as_ushort(__float2half_rn(v.z));
    reinterpret_cast<uint2*>(hi)[i] = H;
}

// ---------------- common GEMM machinery ----------------
#define BM 128
#define BN 128
#define BK 64
#define NSTAGE 3
#define TILE_B 16384                 // 128 rows x 128B (BK=64 fp16), SW128

__device__ __forceinline__ uint32_t s2u(const void* p) {
    uint32_t r;
    asm("{ .reg .u64 t; cvta.to.shared.u64 t, %1; cvt.u32.u64 %0, t; }" : "=r"(r) : "l"(p));
    return r;
}

#define LDSM4(r, a) asm volatile( \
    "ldmatrix.sync.aligned.m8n8.x4.shared.b16 {%0,%1,%2,%3}, [%4];" \
    : "=r"((r)[0]), "=r"((r)[1]), "=r"((r)[2]), "=r"((r)[3]) : "r"(a))

#define MMA16816(d, a, b) asm volatile( \
    "mma.sync.aligned.m16n8k16.row.col.f32.f16.f16.f32 " \
    "{%0,%1,%2,%3}, {%4,%5,%6,%7}, {%8,%9}, {%0,%1,%2,%3};" \
    : "+f"((d)[0]), "+f"((d)[1]), "+f"((d)[2]), "+f"((d)[3]) \
    : "r"((a)[0]), "r"((a)[1]), "r"((a)[2]), "r"((a)[3]), "r"((b)[0]), "r"((b)[1]))

#define CPA16(s, g) asm volatile( \
    "cp.async.cg.shared.global [%0], [%1], 16;" :: "r"(s), "l"(g))

__device__ __forceinline__ void expert_offsets(const int* __restrict__ counts,
                                               int e, int& start, int& cnt, int& start_cl)
{
    int c[NE];
#pragma unroll
    for (int j = 0; j < NE; ++j) c[j] = counts[j];
    start = 0;
#pragma unroll
    for (int j = 0; j < NE; ++j) if (j < e) start += c[j];
    cnt = c[e];
    start_cl = start;
    if (start_cl > NT - CAP) start_cl = NT - CAP;
    if (start_cl < 0) start_cl = 0;
}

// ================= fused GEMM1+GEMM3: h = silu(x@w1^T) * (x@w3^T) =================
// Stage: Ah | B1 | B3  (3 x 16KB), 3 stages = 147456 B
#define STG13  (3 * TILE_B)
#define SMEM13 (NSTAGE * STG13)

__global__ __launch_bounds__(256, 1)
void gemm13(const __half* __restrict__ Xh,
            const __half* __restrict__ W1, const __half* __restrict__ W3,
            __half* __restrict__ Hh,
            const int* __restrict__ counts)
{
    extern __shared__ char smem[];
    const int tid = threadIdx.x;
    const int e = blockIdx.z, bm = blockIdx.y, bn = blockIdx.x;
    const int K = DIM, N = HID;

    int start, cnt, start_cl;
    expert_offsets(counts, e, start, cnt, start_cl);
    (void)cnt;

    const __half* Ahe = Xh + ((size_t)start_cl + (size_t)bm * BM) * K;
    const __half* B1e = W1 + ((size_t)e * N + (size_t)bn * BN) * K;
    const __half* B3e = W3 + ((size_t)e * N + (size_t)bn * BN) * K;

    const uint32_t sb = s2u(smem);
    const int nch = K / BK;   // 32

    auto load_stage = [&](int st, int cc) {
        const __half* s0 = Ahe + cc * BK;
        const __half* s1 = B1e + cc * BK;
        const __half* s2 = B3e + cc * BK;
        const uint32_t sbase = sb + st * STG13;
#pragma unroll
        for (int j = 0; j < 4; ++j) {
            int idx = tid + j * 256;
            int row = idx >> 3, g = idx & 7;
            uint32_t off = row * 128 + g * 16;
            off ^= (off >> 3) & 0x70;
            size_t go = (size_t)row * K + g * 8;
            CPA16(sbase + 0 * TILE_B + off, s0 + go);
            CPA16(sbase + 1 * TILE_B + off, s1 + go);
            CPA16(sbase + 2 * TILE_B + off, s2 + go);
        }
    };

    const int lane = tid & 31, wid = tid >> 5;
    const int wm = (wid & 3) * 32;
    const int wn = (wid >> 2) * 64;
    const int ln8 = lane & 7, sel = lane >> 3;

    float du[2][8][4], dv[2][8][4];
#pragma unroll
    for (int i = 0; i < 2; ++i)
#pragma unroll
        for (int j = 0; j < 8; ++j)
#pragma unroll
            for (int k = 0; k < 4; ++k) { du[i][j][k] = 0.f; dv[i][j][k] = 0.f; }

    load_stage(0, 0);
    asm volatile("cp.async.commit_group;" ::: "memory");
    load_stage(1, 1);
    asm volatile("cp.async.commit_group;" ::: "memory");

    for (int kc = 0; kc < nch; ++kc) {
        if (kc + 2 < nch) load_stage((kc + 2) % NSTAGE, kc + 2);
        asm volatile("cp.async.commit_group;" ::: "memory");
        asm volatile("cp.async.wait_group 2;" ::: "memory");
        __syncthreads();

        const uint32_t aB = sb + (kc % NSTAGE) * STG13;
        const uint32_t b1B = aB + TILE_B;
        const uint32_t b3B = aB + 2 * TILE_B;

#pragma unroll
        for (int k16 = 0; k16 < 4; ++k16) {
            const int kb = k16 * 32;
            uint32_t af[2][4];
#pragma unroll
            for (int mf = 0; mf < 2; ++mf) {
                uint32_t off = (uint32_t)(wm + mf * 16 + (lane & 15)) * 128
                             + kb + ((lane >> 4) << 4);
                off ^= (off >> 3) & 0x70;
                LDSM4(af[mf], aB + off);
            }
            uint32_t b1f[16], b3f[16];
#pragma unroll
            for (int np = 0; np < 4; ++np) {
                uint32_t off = (uint32_t)(wn + np * 16 + ln8 + ((sel >> 1) << 3)) * 128
                             + kb + ((sel & 1) << 4);
                off ^= (off >> 3) & 0x70;
                LDSM4(b1f + np * 4, b1B + off);
                LDSM4(b3f + np * 4, b3B + off);
            }
#pragma unroll
            for (int mf = 0; mf < 2; ++mf)
#pragma unroll
                for (int nf = 0; nf < 8; ++nf) {
                    MMA16816(du[mf][nf], af[mf], b1f + nf * 2);
                    MMA16816(dv[mf][nf], af[mf], b3f + nf * 2);
                }
        }
        __syncthreads();
    }

    // epilogue: h = silu(u) * v -> fp16
    const int lr = lane >> 2, lc = 2 * (lane & 3);
#pragma unroll
    for (int mf = 0; mf < 2; ++mf) {
#pragma unroll
        for (int p = 0; p < 2; ++p) {
            const int rloc = wm + mf * 16 + lr + p * 8;
            const int mglob = bm * BM + rloc;
            size_t rowb = ((size_t)e * CAP + mglob) * HID + (size_t)bn * BN;
#pragma unroll
            for (int nf = 0; nf < 8; ++nf) {
                float u0 = du[mf][nf][p * 2 + 0], u1 = du[mf][nf][p * 2 + 1];
                float v0 = dv[mf][nf][p * 2 + 0], v1 = dv[mf][nf][p * 2 + 1];
                float h0 = (u0 / (1.f + expf(-u0))) * v0;
                float h1 = (u1 / (1.f + expf(-u1))) * v1;
                *(__half2*)&Hh[rowb + wn + nf * 8 + lc] =
                    __halves2half2(__float2half_rn(h0), __float2half_rn(h1));
            }
        }
    }
}

// ================= GEMM2: out = h @ w2^T (ragged scatter) =================
// Stage: Ah | B (2 x 16KB), 3 stages = 98304 B -> 2 CTAs/SM
#define STG2  (2 * TILE_B)
#define SMEM2 (NSTAGE * STG2)

__global__ __launch_bounds__(256, 2)
void gemm2(const __half* __restrict__ Hh, const __half* __restrict__ W2,
           float* __restrict__ Cout, const int* __restrict__ counts)
{
    extern __shared__ char smem[];
    const int tid = threadIdx.x;
    const int e = blockIdx.z, bm = blockIdx.y, bn = blockIdx.x;
    const int K = HID, N = DIM;

    int start, cnt, start_cl;
    expert_offsets(counts, e, start, cnt, start_cl);
    (void)start_cl;

    const __half* Ahe = Hh + ((size_t)e * CAP + (size_t)bm * BM) * K;
    const __half* Bwe = W2 + ((size_t)e * N + (size_t)bn * BN) * K;

    const uint32_t sb = s2u(smem);
    const int nch = K / BK;   // 22

    auto load_stage = [&](int st, int cc) {
        const __half* s0 = Ahe + cc * BK;
        const __half* s1 = Bwe + cc * BK;
        const uint32_t sbase = sb + st * STG2;
#pragma unroll
        for (int j = 0; j < 4; ++j) {
            int idx = tid + j * 256;
            int row = idx >> 3, g = idx & 7;
            uint32_t off = row * 128 + g * 16;
            off ^= (off >> 3) & 0x70;
            size_t go = (size_t)row * K + g * 8;
            CPA16(sbase + 0 * TILE_B + off, s0 + go);
            CPA16(sbase + 1 * TILE_B + off, s1 + go);
        }
    };

    const int lane = tid & 31, wid = tid >> 5;
    const int wm = (wid & 3) * 32;
    const int wn = (wid >> 2) * 64;
    const int ln8 = lane & 7, sel = lane >> 3;

    float dacc[2][8][4];
#pragma unroll
    for (int i = 0; i < 2; ++i)
#pragma unroll
        for (int j = 0; j < 8; ++j)
#pragma unroll
            for (int k = 0; k < 4; ++k) dacc[i][j][k] = 0.f;

    load_stage(0, 0);
    asm volatile("cp.async.commit_group;" ::: "memory");
    load_stage(1, 1);
    asm volatile("cp.async.commit_group;" ::: "memory");

    for (int kc = 0; kc < nch; ++kc) {
        if (kc + 2 < nch) load_stage((kc + 2) % NSTAGE, kc + 2);
        asm volatile("cp.async.commit_group;" ::: "memory");
        asm volatile("cp.async.wait_group 2;" ::: "memory");
        __syncthreads();

        const uint32_t aB = sb + (kc % NSTAGE) * STG2;
        const uint32_t bB = aB + TILE_B;

#pragma unroll
        for (int k16 = 0; k16 < 4; ++k16) {
            const int kb = k16 * 32;
            uint32_t af[2][4];
#pragma unroll
            for (int mf = 0; mf < 2; ++mf) {
                uint32_t off = (uint32_t)(wm + mf * 16 + (lane & 15)) * 128
                             + kb + ((lane >> 4) << 4);
                off ^= (off >> 3) & 0x70;
                LDSM4(af[mf], aB + off);
            }
            uint32_t bfr[16];
#pragma unroll
            for (int np = 0; np < 4; ++np) {
                uint32_t off = (uint32_t)(wn + np * 16 + ln8 + ((sel >> 1) << 3)) * 128
                             + kb + ((sel & 1) << 4);
                off ^= (off >> 3) & 0x70;
                LDSM4(bfr + np * 4, bB + off);
            }
#pragma unroll
            for (int mf = 0; mf < 2; ++mf)
#pragma unroll
                for (int nf = 0; nf < 8; ++nf)
                    MMA16816(dacc[mf][nf], af[mf], bfr + nf * 2);
        }
        __syncthreads();
    }

    const int lr = lane >> 2, lc = 2 * (lane & 3);
#pragma unroll
    for (int mf = 0; mf < 2; ++mf) {
#pragma unroll
        for (int p = 0; p < 2; ++p) {
            const int rloc = wm + mf * 16 + lr + p * 8;
            const int mglob = bm * BM + rloc;
            if (mglob < cnt) {
                int orow = start + mglob;
                if (orow < 0) orow = 0;
                if (orow > NT - 1) orow = NT - 1;
#pragma unroll
                for (int nf = 0; nf < 8; ++nf) {
                    *(float2*)&Cout[(size_t)orow * DIM + bn * BN + wn + nf * 8 + lc] =
                        make_float2(dacc[mf][nf][p * 2 + 0], dacc[mf][nf][p * 2 + 1]);
                }
            }
        }
    }
}

// ---------------- host launcher ----------------
extern "C" void kernel_launch(void* const* d_in, const int* in_sizes, int n_in,
                              void* d_out, int out_size)
{
    const float* x      = (const float*)d_in[0];
    const int*   counts = (const int*)  d_in[1];
    const float* w1     = (const float*)d_in[2];
    const float* w2     = (const float*)d_in[3];
    const float* w3     = (const float*)d_in[4];
    float* out = (float*)d_out;

    void *xh, *w1h, *w3h, *w2h, *hh;
    cudaGetSymbolAddress(&xh,  g_xh);
    cudaGetSymbolAddress(&w1h, g_w1h);
    cudaGetSymbolAddress(&w3h, g_w3h);
    cudaGetSymbolAddress(&w2h, g_w2h);
    cudaGetSymbolAddress(&hh,  g_hh);

    cudaMemsetAsync(out, 0, (size_t)out_size * sizeof(float));

    const int nx4 = NT * DIM / 4;
    const int nw4 = NE * HID * DIM / 4;
    cvt_round<<<(nx4 + 255) / 256, 256>>>(x,  (__half*)xh,  nx4);
    cvt_round<<<(nw4 + 255) / 256, 256>>>(w1, (__half*)w1h, nw4);
    cvt_round<<<(nw4 + 255) / 256, 256>>>(w3, (__half*)w3h, nw4);
    cvt_round<<<(nw4 + 255) / 256, 256>>>(w2, (__half*)w2h, nw4);

    cudaFuncSetAttribute(gemm13, cudaFuncAttributeMaxDynamicSharedMemorySize, SMEM13);
    cudaFuncSetAttribute(gemm2,  cudaFuncAttributeMaxDynamicSharedMemorySize, SMEM2);

    dim3 blk(256);
    dim3 gA(HID / BN, CAP / BM, NE);   // 11 x 8 x 8
    dim3 gB(DIM / BN, CAP / BM, NE);   // 16 x 8 x 8

    gemm13<<<gA, blk, SMEM13>>>((const __half*)xh, (const __half*)w1h,
                                (const __half*)w3h, (__half*)hh, counts);
    gemm2<<<gB, blk, SMEM2>>>((const __half*)hh, (const __half*)w2h, out, counts);
}

// round 12
// speedup vs baseline: 7.1433x; 1.0533x over previous
#include <cuda_runtime.h>
#include <cuda_fp16.h>
#include <stdint.h>
#include <math.h>

#define NT   8192
#define DIM  2048
#define HID  1408
#define NE   8
#define CAP  1024

// ---------------- device scratch ----------------
__device__ __half g_xh[(size_t)NT * DIM];           // x fp16
__device__ __half g_hh[(size_t)NT * HID];           // h fp16
__device__ __half g_w1h[(size_t)NE * HID * DIM];
__device__ __half g_w3h[(size_t)NE * HID * DIM];
__device__ __half g_w2h[(size_t)NE * DIM * HID];

// ---------------- fp32 -> fp16 round (4x ILP) ----------------
__global__ __launch_bounds__(256)
void cvt_round(const float* __restrict__ src, __half* __restrict__ dst, int n4)
{
    int base = blockIdx.x * 1024 + threadIdx.x;
    float4 v[4];
    int idx[4];
    bool ok[4];
#pragma unroll
    for (int j = 0; j < 4; ++j) {
        idx[j] = base + j * 256;
        ok[j] = idx[j] < n4;
        if (ok[j]) v[j] = reinterpret_cast<const float4*>(src)[idx[j]];
    }
#pragma unroll
    for (int j = 0; j < 4; ++j) {
        if (!ok[j]) continue;
        uint2 H;
        H.x = ((uint32_t)__half_as_ushort(__float2half_rn(v[j].y)) << 16) |
              __half_as_ushort(__float2half_rn(v[j].x));
        H.y = ((uint32_t)__half_as_ushort(__float2half_rn(v[j].w)) << 16) |
              __half_as_ushort(__float2half_rn(v[j].z));
        reinterpret_cast<uint2*>(dst)[idx[j]] = H;
    }
}

// ---------------- common GEMM machinery ----------------
#define BM 128
#define BN 128
#define BK 64
#define NSTAGE 3
#define TILE_B 16384                 // 128 rows x 128B (BK=64 fp16), SW128

__device__ __forceinline__ uint32_t s2u(const void* p) {
    uint32_t r;
    asm("{ .reg .u64 t; cvta.to.shared.u64 t, %1; cvt.u32.u64 %0, t; }" : "=r"(r) : "l"(p));
    return r;
}

#define LDSM4(r, a) asm volatile( \
    "ldmatrix.sync.aligned.m8n8.x4.shared.b16 {%0,%1,%2,%3}, [%4];" \
    : "=r"((r)[0]), "=r"((r)[1]), "=r"((r)[2]), "=r"((r)[3]) : "r"(a))

#define MMA16816(d, a, b) asm volatile( \
    "mma.sync.aligned.m16n8k16.row.col.f32.f16.f16.f32 " \
    "{%0,%1,%2,%3}, {%4,%5,%6,%7}, {%8,%9}, {%0,%1,%2,%3};" \
    : "+f"((d)[0]), "+f"((d)[1]), "+f"((d)[2]), "+f"((d)[3]) \
    : "r"((a)[0]), "r"((a)[1]), "r"((a)[2]), "r"((a)[3]), "r"((b)[0]), "r"((b)[1]))

#define CPA16(s, g) asm volatile( \
    "cp.async.cg.shared.global [%0], [%1], 16;" :: "r"(s), "l"(g))

#define CP_COMMIT() asm volatile("cp.async.commit_group;" ::: "memory")
#define CP_WAIT1()  asm volatile("cp.async.wait_group 1;" ::: "memory")

__device__ __forceinline__ void expert_offsets(const int* __restrict__ counts,
                                               int e, int& start, int& cnt, int& start_cl)
{
    int c[NE];
#pragma unroll
    for (int j = 0; j < NE; ++j) c[j] = counts[j];
    start = 0;
#pragma unroll
    for (int j = 0; j < NE; ++j) if (j < e) start += c[j];
    cnt = c[e];
    start_cl = start;
    if (start_cl > NT - CAP) start_cl = NT - CAP;
    if (start_cl < 0) start_cl = 0;
}

// ================= fused GEMM1+GEMM3: h = silu(x@w1^T) * (x@w3^T) =================
#define STG13  (3 * TILE_B)
#define SMEM13 (NSTAGE * STG13)

__global__ __launch_bounds__(256, 1)
void gemm13(const __half* __restrict__ Xh,
            const __half* __restrict__ W1, const __half* __restrict__ W3,
            __half* __restrict__ Hh,
            const int* __restrict__ counts)
{
    extern __shared__ char smem[];
    const int tid = threadIdx.x;
    const int e = blockIdx.z, bm = blockIdx.y, bn = blockIdx.x;
    const int K = DIM, N = HID;

    int start, cnt, start_cl;
    expert_offsets(counts, e, start, cnt, start_cl);
    (void)cnt; (void)start;

    const __half* Ahe = Xh + ((size_t)start_cl + (size_t)bm * BM) * K;
    const __half* B1e = W1 + ((size_t)e * N + (size_t)bn * BN) * K;
    const __half* B3e = W3 + ((size_t)e * N + (size_t)bn * BN) * K;

    const uint32_t sb = s2u(smem);
    const int nch = K / BK;   // 32

    auto load_stage = [&](int st, int cc) {
        const __half* s0 = Ahe + cc * BK;
        const __half* s1 = B1e + cc * BK;
        const __half* s2 = B3e + cc * BK;
        const uint32_t sbase = sb + st * STG13;
#pragma unroll
        for (int j = 0; j < 4; ++j) {
            int idx = tid + j * 256;
            int row = idx >> 3, g = idx & 7;
            uint32_t off = row * 128 + g * 16;
            off ^= (off >> 3) & 0x70;
            size_t go = (size_t)row * K + g * 8;
            CPA16(sbase + 0 * TILE_B + off, s0 + go);
            CPA16(sbase + 1 * TILE_B + off, s1 + go);
            CPA16(sbase + 2 * TILE_B + off, s2 + go);
        }
    };

    const int lane = tid & 31, wid = tid >> 5;
    const int wm = (wid & 3) * 32;
    const int wn = (wid >> 2) * 64;
    const int ln8 = lane & 7, sel = lane >> 3;

    float du[2][8][4], dv[2][8][4];
#pragma unroll
    for (int i = 0; i < 2; ++i)
#pragma unroll
        for (int j = 0; j < 8; ++j)
#pragma unroll
            for (int k = 0; k < 4; ++k) { du[i][j][k] = 0.f; dv[i][j][k] = 0.f; }

    load_stage(0, 0); CP_COMMIT();
    load_stage(1, 1); CP_COMMIT();

    for (int kc = 0; kc < nch; ++kc) {
        CP_WAIT1();            // oldest group (stage kc) landed
        __syncthreads();       // all warps done with chunk kc-1 -> stage (kc+2)%3 free
        if (kc + 2 < nch) load_stage((kc + 2) % NSTAGE, kc + 2);
        CP_COMMIT();

        const uint32_t aB = sb + (kc % NSTAGE) * STG13;
        const uint32_t b1B = aB + TILE_B;
        const uint32_t b3B = aB + 2 * TILE_B;

#pragma unroll
        for (int k16 = 0; k16 < 4; ++k16) {
            const int kb = k16 * 32;
            uint32_t af[2][4];
#pragma unroll
            for (int mf = 0; mf < 2; ++mf) {
                uint32_t off = (uint32_t)(wm + mf * 16 + (lane & 15)) * 128
                             + kb + ((lane >> 4) << 4);
                off ^= (off >> 3) & 0x70;
                LDSM4(af[mf], aB + off);
            }
            uint32_t b1f[16], b3f[16];
#pragma unroll
            for (int np = 0; np < 4; ++np) {
                uint32_t off = (uint32_t)(wn + np * 16 + ln8 + ((sel >> 1) << 3)) * 128
                             + kb + ((sel & 1) << 4);
                off ^= (off >> 3) & 0x70;
                LDSM4(b1f + np * 4, b1B + off);
                LDSM4(b3f + np * 4, b3B + off);
            }
#pragma unroll
            for (int mf = 0; mf < 2; ++mf)
#pragma unroll
                for (int nf = 0; nf < 8; ++nf) {
                    MMA16816(du[mf][nf], af[mf], b1f + nf * 2);
                    MMA16816(dv[mf][nf], af[mf], b3f + nf * 2);
                }
        }
    }

    __syncthreads();

    // epilogue: h = silu(u) * v -> fp16
    const int lr = lane >> 2, lc = 2 * (lane & 3);
#pragma unroll
    for (int mf = 0; mf < 2; ++mf) {
#pragma unroll
        for (int p = 0; p < 2; ++p) {
            const int rloc = wm + mf * 16 + lr + p * 8;
            const int mglob = bm * BM + rloc;
            size_t rowb = ((size_t)e * CAP + mglob) * HID + (size_t)bn * BN;
#pragma unroll
            for (int nf = 0; nf < 8; ++nf) {
                float u0 = du[mf][nf][p * 2 + 0], u1 = du[mf][nf][p * 2 + 1];
                float v0 = dv[mf][nf][p * 2 + 0], v1 = dv[mf][nf][p * 2 + 1];
                float h0 = (u0 / (1.f + __expf(-u0))) * v0;
                float h1 = (u1 / (1.f + __expf(-u1))) * v1;
                *(__half2*)&Hh[rowb + wn + nf * 8 + lc] =
                    __halves2half2(__float2half_rn(h0), __float2half_rn(h1));
            }
        }
    }
}

// ================= GEMM2: out = h @ w2^T (ragged scatter) =================
#define STG2  (2 * TILE_B)
#define SMEM2 (NSTAGE * STG2)

__global__ __launch_bounds__(256, 2)
void gemm2(const __half* __restrict__ Hh, const __half* __restrict__ W2,
           float* __restrict__ Cout, const int* __restrict__ counts)
{
    extern __shared__ char smem[];
    const int tid = threadIdx.x;
    const int e = blockIdx.z, bm = blockIdx.y, bn = blockIdx.x;
    const int K = HID, N = DIM;

    int start, cnt, start_cl;
    expert_offsets(counts, e, start, cnt, start_cl);
    (void)start_cl;

    const __half* Ahe = Hh + ((size_t)e * CAP + (size_t)bm * BM) * K;
    const __half* Bwe = W2 + ((size_t)e * N + (size_t)bn * BN) * K;

    const uint32_t sb = s2u(smem);
    const int nch = K / BK;   // 22

    auto load_stage = [&](int st, int cc) {
        const __half* s0 = Ahe + cc * BK;
        const __half* s1 = Bwe + cc * BK;
        const uint32_t sbase = sb + st * STG2;
#pragma unroll
        for (int j = 0; j < 4; ++j) {
            int idx = tid + j * 256;
            int row = idx >> 3, g = idx & 7;
            uint32_t off = row * 128 + g * 16;
            off ^= (off >> 3) & 0x70;
            size_t go = (size_t)row * K + g * 8;
            CPA16(sbase + 0 * TILE_B + off, s0 + go);
            CPA16(sbase + 1 * TILE_B + off, s1 + go);
        }
    };

    const int lane = tid & 31, wid = tid >> 5;
    const int wm = (wid & 3) * 32;
    const int wn = (wid >> 2) * 64;
    const int ln8 = lane & 7, sel = lane >> 3;

    float dacc[2][8][4];
#pragma unroll
    for (int i = 0; i < 2; ++i)
#pragma unroll
        for (int j = 0; j < 8; ++j)
#pragma unroll
            for (int k = 0; k < 4; ++k) dacc[i][j][k] = 0.f;

    load_stage(0, 0); CP_COMMIT();
    load_stage(1, 1); CP_COMMIT();

    for (int kc = 0; kc < nch; ++kc) {
        CP_WAIT1();
        __syncthreads();
        if (kc + 2 < nch) load_stage((kc + 2) % NSTAGE, kc + 2);
        CP_COMMIT();

        const uint32_t aB = sb + (kc % NSTAGE) * STG2;
        const uint32_t bB = aB + TILE_B;

#pragma unroll
        for (int k16 = 0; k16 < 4; ++k16) {
            const int kb = k16 * 32;
            uint32_t af[2][4];
#pragma unroll
            for (int mf = 0; mf < 2; ++mf) {
                uint32_t off = (uint32_t)(wm + mf * 16 + (lane & 15)) * 128
                             + kb + ((lane >> 4) << 4);
                off ^= (off >> 3) & 0x70;
                LDSM4(af[mf], aB + off);
            }
            uint32_t bfr[16];
#pragma unroll
            for (int np = 0; np < 4; ++np) {
                uint32_t off = (uint32_t)(wn + np * 16 + ln8 + ((sel >> 1) << 3)) * 128
                             + kb + ((sel & 1) << 4);
                off ^= (off >> 3) & 0x70;
                LDSM4(bfr + np * 4, bB + off);
            }
#pragma unroll
            for (int mf = 0; mf < 2; ++mf)
#pragma unroll
                for (int nf = 0; nf < 8; ++nf)
                    MMA16816(dacc[mf][nf], af[mf], bfr + nf * 2);
        }
    }

    const int lr = lane >> 2, lc = 2 * (lane & 3);
#pragma unroll
    for (int mf = 0; mf < 2; ++mf) {
#pragma unroll
        for (int p = 0; p < 2; ++p) {
            const int rloc = wm + mf * 16 + lr + p * 8;
            const int mglob = bm * BM + rloc;
            if (mglob < cnt) {
                int orow = start + mglob;
                if (orow < 0) orow = 0;
                if (orow > NT - 1) orow = NT - 1;
#pragma unroll
                for (int nf = 0; nf < 8; ++nf) {
                    *(float2*)&Cout[(size_t)orow * DIM + bn * BN + wn + nf * 8 + lc] =
                        make_float2(dacc[mf][nf][p * 2 + 0], dacc[mf][nf][p * 2 + 1]);
                }
            } else {
                // balanced routing never reaches here; zero-fill replaces the memset
                int orow = start + mglob;
                if (orow < NT) {
#pragma unroll
                    for (int nf = 0; nf < 8; ++nf) {
                        *(float2*)&Cout[(size_t)orow * DIM + bn * BN + wn + nf * 8 + lc] =
                            make_float2(0.f, 0.f);
                    }
                }
            }
        }
    }
}

// ---------------- host launcher ----------------
extern "C" void kernel_launch(void* const* d_in, const int* in_sizes, int n_in,
                              void* d_out, int out_size)
{
    const float* x      = (const float*)d_in[0];
    const int*   counts = (const int*)  d_in[1];
    const float* w1     = (const float*)d_in[2];
    const float* w2     = (const float*)d_in[3];
    const float* w3     = (const float*)d_in[4];
    float* out = (float*)d_out;

    void *xh, *w1h, *w3h, *w2h, *hh;
    cudaGetSymbolAddress(&xh,  g_xh);
    cudaGetSymbolAddress(&w1h, g_w1h);
    cudaGetSymbolAddress(&w3h, g_w3h);
    cudaGetSymbolAddress(&w2h, g_w2h);
    cudaGetSymbolAddress(&hh,  g_hh);

    const int nx4 = NT * DIM / 4;
    const int nw4 = NE * HID * DIM / 4;
    cvt_round<<<(nx4 + 1023) / 1024, 256>>>(x,  (__half*)xh,  nx4);
    cvt_round<<<(nw4 + 1023) / 1024, 256>>>(w1, (__half*)w1h, nw4);
    cvt_round<<<(nw4 + 1023) / 1024, 256>>>(w3, (__half*)w3h, nw4);
    cvt_round<<<(nw4 + 1023) / 1024, 256>>>(w2, (__half*)w2h, nw4);

    cudaFuncSetAttribute(gemm13, cudaFuncAttributeMaxDynamicSharedMemorySize, SMEM13);
    cudaFuncSetAttribute(gemm2,  cudaFuncAttributeMaxDynamicSharedMemorySize, SMEM2);

    dim3 blk(256);
    dim3 gA(HID / BN, CAP / BM, NE);   // 11 x 8 x 8
    dim3 gB(DIM / BN, CAP / BM, NE);   // 16 x 8 x 8

    gemm13<<<gA, blk, SMEM13>>>((const __half*)xh, (const __half*)w1h,
                                (const __half*)w3h, (__half*)hh, counts);
    gemm2<<<gB, blk, SMEM2>>>((const __half*)hh, (const __half*)w2h, out, counts);
}

// round 13
// speedup vs baseline: 7.2285x; 1.0119x over previous
#include <cuda_runtime.h>
#include <cuda_fp16.h>
#include <stdint.h>
#include <math.h>

#define NT   8192
#define DIM  2048
#define HID  1408
#define NE   8
#define CAP  1024

// ---------------- device scratch ----------------
__device__ __half g_xh[(size_t)NT * DIM];           // x fp16
__device__ __half g_hh[(size_t)NT * HID];           // h fp16
__device__ __half g_w1h[(size_t)NE * HID * DIM];
__device__ __half g_w3h[(size_t)NE * HID * DIM];
__device__ __half g_w2h[(size_t)NE * DIM * HID];

__device__ __forceinline__ uint2 pack_h4(float4 v) {
    uint2 H;
    H.x = ((uint32_t)__half_as_ushort(__float2half_rn(v.y)) << 16) |
          __half_as_ushort(__float2half_rn(v.x));
    H.y = ((uint32_t)__half_as_ushort(__float2half_rn(v.w)) << 16) |
          __half_as_ushort(__float2half_rn(v.z));
    return H;
}

// ---------------- fp32 -> fp16 round (8x ILP) ----------------
__global__ __launch_bounds__(256)
void cvt_round(const float* __restrict__ src, __half* __restrict__ dst, int n4)
{
    int base = blockIdx.x * 2048 + threadIdx.x;
    float4 v[8];
    int idx[8];
    bool ok[8];
#pragma unroll
    for (int j = 0; j < 8; ++j) {
        idx[j] = base + j * 256;
        ok[j] = idx[j] < n4;
        if (ok[j]) v[j] = reinterpret_cast<const float4*>(src)[idx[j]];
    }
#pragma unroll
    for (int j = 0; j < 8; ++j)
        if (ok[j]) reinterpret_cast<uint2*>(dst)[idx[j]] = pack_h4(v[j]);
}

// ---------------- common GEMM machinery ----------------
#define BM 128
#define BN 128
#define BK 64
#define NSTAGE 3
#define TILE_B 16384                 // 128 rows x 128B (BK=64 fp16), SW128

__device__ __forceinline__ uint32_t s2u(const void* p) {
    uint32_t r;
    asm("{ .reg .u64 t; cvta.to.shared.u64 t, %1; cvt.u32.u64 %0, t; }" : "=r"(r) : "l"(p));
    return r;
}

#define LDSM4(r, a) asm volatile( \
    "ldmatrix.sync.aligned.m8n8.x4.shared.b16 {%0,%1,%2,%3}, [%4];" \
    : "=r"((r)[0]), "=r"((r)[1]), "=r"((r)[2]), "=r"((r)[3]) : "r"(a))

#define MMA16816(d, a, b) asm volatile( \
    "mma.sync.aligned.m16n8k16.row.col.f32.f16.f16.f32 " \
    "{%0,%1,%2,%3}, {%4,%5,%6,%7}, {%8,%9}, {%0,%1,%2,%3};" \
    : "+f"((d)[0]), "+f"((d)[1]), "+f"((d)[2]), "+f"((d)[3]) \
    : "r"((a)[0]), "r"((a)[1]), "r"((a)[2]), "r"((a)[3]), "r"((b)[0]), "r"((b)[1]))

#define CPA16(s, g) asm volatile( \
    "cp.async.cg.shared.global [%0], [%1], 16;" :: "r"(s), "l"(g))

#define CP_COMMIT() asm volatile("cp.async.commit_group;" ::: "memory")
#define CP_WAIT1()  asm volatile("cp.async.wait_group 1;" ::: "memory")

__device__ __forceinline__ void expert_offsets(const int* __restrict__ counts,
                                               int e, int& start, int& cnt, int& start_cl)
{
    int c[NE];
#pragma unroll
    for (int j = 0; j < NE; ++j) c[j] = counts[j];
    start = 0;
#pragma unroll
    for (int j = 0; j < NE; ++j) if (j < e) start += c[j];
    cnt = c[e];
    start_cl = start;
    if (start_cl > NT - CAP) start_cl = NT - CAP;
    if (start_cl < 0) start_cl = 0;
}

// ================= fused GEMM1+GEMM3: h = silu(x@w1^T) * (x@w3^T) =================
// Also converts w2 fp32->fp16 inside the mainloop (software-pipelined, 1 float4
// per thread per chunk; 704 CTAs x 256 thr x 32 chunks == NE*DIM*HID/4 exactly).
#define STG13  (3 * TILE_B)
#define SMEM13 (NSTAGE * STG13)
#define W2_PER_CTA 8192              // float4 elements converted per CTA

__global__ __launch_bounds__(256, 1)
void gemm13(const __half* __restrict__ Xh,
            const __half* __restrict__ W1, const __half* __restrict__ W3,
            __half* __restrict__ Hh,
            const float* __restrict__ W2f, __half* __restrict__ W2h,
            const int* __restrict__ counts)
{
    extern __shared__ char smem[];
    const int tid = threadIdx.x;
    const int e = blockIdx.z, bm = blockIdx.y, bn = blockIdx.x;
    const int K = DIM, N = HID;

    int start, cnt, start_cl;
    expert_offsets(counts, e, start, cnt, start_cl);
    (void)cnt; (void)start;

    const __half* Ahe = Xh + ((size_t)start_cl + (size_t)bm * BM) * K;
    const __half* B1e = W1 + ((size_t)e * N + (size_t)bn * BN) * K;
    const __half* B3e = W3 + ((size_t)e * N + (size_t)bn * BN) * K;

    const uint32_t sb = s2u(smem);
    const int nch = K / BK;   // 32

    auto load_stage = [&](int st, int cc) {
        const __half* s0 = Ahe + cc * BK;
        const __half* s1 = B1e + cc * BK;
        const __half* s2 = B3e + cc * BK;
        const uint32_t sbase = sb + st * STG13;
#pragma unroll
        for (int j = 0; j < 4; ++j) {
            int idx = tid + j * 256;
            int row = idx >> 3, g = idx & 7;
            uint32_t off = row * 128 + g * 16;
            off ^= (off >> 3) & 0x70;
            size_t go = (size_t)row * K + g * 8;
            CPA16(sbase + 0 * TILE_B + off, s0 + go);
            CPA16(sbase + 1 * TILE_B + off, s1 + go);
            CPA16(sbase + 2 * TILE_B + off, s2 + go);
        }
    };

    const int lane = tid & 31, wid = tid >> 5;
    const int wm = (wid & 3) * 32;
    const int wn = (wid >> 2) * 64;
    const int ln8 = lane & 7, sel = lane >> 3;

    float du[2][8][4], dv[2][8][4];
#pragma unroll
    for (int i = 0; i < 2; ++i)
#pragma unroll
        for (int j = 0; j < 8; ++j)
#pragma unroll
            for (int k = 0; k < 4; ++k) { du[i][j][k] = 0.f; dv[i][j][k] = 0.f; }

    // fused w2 conversion state (prefetch chunk 0)
    const int cta = blockIdx.x + gridDim.x * (blockIdx.y + gridDim.y * blockIdx.z);
    const size_t cbase = (size_t)cta * W2_PER_CTA + tid;
    const float4* w2src = reinterpret_cast<const float4*>(W2f);
    uint2* w2dst = reinterpret_cast<uint2*>(W2h);
    float4 cv = w2src[cbase];

    load_stage(0, 0); CP_COMMIT();
    load_stage(1, 1); CP_COMMIT();

    for (int kc = 0; kc < nch; ++kc) {
        CP_WAIT1();            // oldest group (stage kc) landed
        __syncthreads();       // all warps done with chunk kc-1 -> stage (kc+2)%3 free
        if (kc + 2 < nch) load_stage((kc + 2) % NSTAGE, kc + 2);
        CP_COMMIT();

        // w2 convert: prefetch next chunk's element, store current (hidden by MMAs)
        float4 nv;
        if (kc + 1 < nch) nv = w2src[cbase + (size_t)(kc + 1) * 256];
        w2dst[cbase + (size_t)kc * 256] = pack_h4(cv);
        cv = nv;

        const uint32_t aB = sb + (kc % NSTAGE) * STG13;
        const uint32_t b1B = aB + TILE_B;
        const uint32_t b3B = aB + 2 * TILE_B;

#pragma unroll
        for (int k16 = 0; k16 < 4; ++k16) {
            const int kb = k16 * 32;
            uint32_t af[2][4];
#pragma unroll
            for (int mf = 0; mf < 2; ++mf) {
                uint32_t off = (uint32_t)(wm + mf * 16 + (lane & 15)) * 128
                             + kb + ((lane >> 4) << 4);
                off ^= (off >> 3) & 0x70;
                LDSM4(af[mf], aB + off);
            }
            uint32_t b1f[16], b3f[16];
#pragma unroll
            for (int np = 0; np < 4; ++np) {
                uint32_t off = (uint32_t)(wn + np * 16 + ln8 + ((sel >> 1) << 3)) * 128
                             + kb + ((sel & 1) << 4);
                off ^= (off >> 3) & 0x70;
                LDSM4(b1f + np * 4, b1B + off);
                LDSM4(b3f + np * 4, b3B + off);
            }
#pragma unroll
            for (int mf = 0; mf < 2; ++mf)
#pragma unroll
                for (int nf = 0; nf < 8; ++nf) {
                    MMA16816(du[mf][nf], af[mf], b1f + nf * 2);
                    MMA16816(dv[mf][nf], af[mf], b3f + nf * 2);
                }
        }
    }

    __syncthreads();

    // epilogue: h = silu(u) * v -> fp16
    const int lr = lane >> 2, lc = 2 * (lane & 3);
#pragma unroll
    for (int mf = 0; mf < 2; ++mf) {
#pragma unroll
        for (int p = 0; p < 2; ++p) {
            const int rloc = wm + mf * 16 + lr + p * 8;
            const int mglob = bm * BM + rloc;
            size_t rowb = ((size_t)e * CAP + mglob) * HID + (size_t)bn * BN;
#pragma unroll
            for (int nf = 0; nf < 8; ++nf) {
                float u0 = du[mf][nf][p * 2 + 0], u1 = du[mf][nf][p * 2 + 1];
                float v0 = dv[mf][nf][p * 2 + 0], v1 = dv[mf][nf][p * 2 + 1];
                float h0 = (u0 / (1.f + __expf(-u0))) * v0;
                float h1 = (u1 / (1.f + __expf(-u1))) * v1;
                *(__half2*)&Hh[rowb + wn + nf * 8 + lc] =
                    __halves2half2(__float2half_rn(h0), __float2half_rn(h1));
            }
        }
    }
}

// ================= GEMM2: out = h @ w2^T (ragged scatter) =================
#define STG2  (2 * TILE_B)
#define SMEM2 (NSTAGE * STG2)

__global__ __launch_bounds__(256, 2)
void gemm2(const __half* __restrict__ Hh, const __half* __restrict__ W2,
           float* __restrict__ Cout, const int* __restrict__ counts)
{
    extern __shared__ char smem[];
    const int tid = threadIdx.x;
    const int e = blockIdx.z, bm = blockIdx.y, bn = blockIdx.x;
    const int K = HID, N = DIM;

    int start, cnt, start_cl;
    expert_offsets(counts, e, start, cnt, start_cl);
    (void)start_cl;

    const __half* Ahe = Hh + ((size_t)e * CAP + (size_t)bm * BM) * K;
    const __half* Bwe = W2 + ((size_t)e * N + (size_t)bn * BN) * K;

    const uint32_t sb = s2u(smem);
    const int nch = K / BK;   // 22

    auto load_stage = [&](int st, int cc) {
        const __half* s0 = Ahe + cc * BK;
        const __half* s1 = Bwe + cc * BK;
        const uint32_t sbase = sb + st * STG2;
#pragma unroll
        for (int j = 0; j < 4; ++j) {
            int idx = tid + j * 256;
            int row = idx >> 3, g = idx & 7;
            uint32_t off = row * 128 + g * 16;
            off ^= (off >> 3) & 0x70;
            size_t go = (size_t)row * K + g * 8;
            CPA16(sbase + 0 * TILE_B + off, s0 + go);
            CPA16(sbase + 1 * TILE_B + off, s1 + go);
        }
    };

    const int lane = tid & 31, wid = tid >> 5;
    const int wm = (wid & 3) * 32;
    const int wn = (wid >> 2) * 64;
    const int ln8 = lane & 7, sel = lane >> 3;

    float dacc[2][8][4];
#pragma unroll
    for (int i = 0; i < 2; ++i)
#pragma unroll
        for (int j = 0; j < 8; ++j)
#pragma unroll
            for (int k = 0; k < 4; ++k) dacc[i][j][k] = 0.f;

    load_stage(0, 0); CP_COMMIT();
    load_stage(1, 1); CP_COMMIT();

    for (int kc = 0; kc < nch; ++kc) {
        CP_WAIT1();
        __syncthreads();
        if (kc + 2 < nch) load_stage((kc + 2) % NSTAGE, kc + 2);
        CP_COMMIT();

        const uint32_t aB = sb + (kc % NSTAGE) * STG2;
        const uint32_t bB = aB + TILE_B;

#pragma unroll
        for (int k16 = 0; k16 < 4; ++k16) {
            const int kb = k16 * 32;
            uint32_t af[2][4];
#pragma unroll
            for (int mf = 0; mf < 2; ++mf) {
                uint32_t off = (uint32_t)(wm + mf * 16 + (lane & 15)) * 128
                             + kb + ((lane >> 4) << 4);
                off ^= (off >> 3) & 0x70;
                LDSM4(af[mf], aB + off);
            }
            uint32_t bfr[16];
#pragma unroll
            for (int np = 0; np < 4; ++np) {
                uint32_t off = (uint32_t)(wn + np * 16 + ln8 + ((sel >> 1) << 3)) * 128
                             + kb + ((sel & 1) << 4);
                off ^= (off >> 3) & 0x70;
                LDSM4(bfr + np * 4, bB + off);
            }
#pragma unroll
            for (int mf = 0; mf < 2; ++mf)
#pragma unroll
                for (int nf = 0; nf < 8; ++nf)
                    MMA16816(dacc[mf][nf], af[mf], bfr + nf * 2);
        }
    }

    const int lr = lane >> 2, lc = 2 * (lane & 3);
#pragma unroll
    for (int mf = 0; mf < 2; ++mf) {
#pragma unroll
        for (int p = 0; p < 2; ++p) {
            const int rloc = wm + mf * 16 + lr + p * 8;
            const int mglob = bm * BM + rloc;
            if (mglob < cnt) {
                int orow = start + mglob;
                if (orow < 0) orow = 0;
                if (orow > NT - 1) orow = NT - 1;
#pragma unroll
                for (int nf = 0; nf < 8; ++nf) {
                    *(float2*)&Cout[(size_t)orow * DIM + bn * BN + wn + nf * 8 + lc] =
                        make_float2(dacc[mf][nf][p * 2 + 0], dacc[mf][nf][p * 2 + 1]);
                }
            } else {
                // balanced routing never reaches here; zero-fill replaces the memset
                int orow = start + mglob;
                if (orow < NT) {
#pragma unroll
                    for (int nf = 0; nf < 8; ++nf) {
                        *(float2*)&Cout[(size_t)orow * DIM + bn * BN + wn + nf * 8 + lc] =
                            make_float2(0.f, 0.f);
                    }
                }
            }
        }
    }
}

// ---------------- host launcher ----------------
extern "C" void kernel_launch(void* const* d_in, const int* in_sizes, int n_in,
                              void* d_out, int out_size)
{
    const float* x      = (const float*)d_in[0];
    const int*   counts = (const int*)  d_in[1];
    const float* w1     = (const float*)d_in[2];
    const float* w2     = (const float*)d_in[3];
    const float* w3     = (const float*)d_in[4];
    float* out = (float*)d_out;

    void *xh, *w1h, *w3h, *w2h, *hh;
    cudaGetSymbolAddress(&xh,  g_xh);
    cudaGetSymbolAddress(&w1h, g_w1h);
    cudaGetSymbolAddress(&w3h, g_w3h);
    cudaGetSymbolAddress(&w2h, g_w2h);
    cudaGetSymbolAddress(&hh,  g_hh);

    const int nx4 = NT * DIM / 4;            // 4,194,304 (div 2048)
    const int nw4 = NE * HID * DIM / 4;      // 5,767,168 (div 2048)
    cvt_round<<<nx4 / 2048, 256>>>(x,  (__half*)xh,  nx4);
    cvt_round<<<nw4 / 2048, 256>>>(w1, (__half*)w1h, nw4);
    cvt_round<<<nw4 / 2048, 256>>>(w3, (__half*)w3h, nw4);
    // w2 conversion is fused into gemm13

    cudaFuncSetAttribute(gemm13, cudaFuncAttributeMaxDynamicSharedMemorySize, SMEM13);
    cudaFuncSetAttribute(gemm2,  cudaFuncAttributeMaxDynamicSharedMemorySize, SMEM2);

    dim3 blk(256);
    dim3 gA(HID / BN, CAP / BM, NE);   // 11 x 8 x 8 = 704
    dim3 gB(DIM / BN, CAP / BM, NE);   // 16 x 8 x 8 = 1024

    gemm13<<<gA, blk, SMEM13>>>((const __half*)xh, (const __half*)w1h,
                                (const __half*)w3h, (__half*)hh,
                                w2, (__half*)w2h, counts);
    gemm2<<<gB, blk, SMEM2>>>((const __half*)hh, (const __half*)w2h, out, counts);
}